// round 2
// baseline (speedup 1.0000x reference)
#include <cuda_runtime.h>
#include <math.h>

// Problem constants
#define Bn 8
#define Cn 384
#define NQ 4096
#define NK 1024
#define Hn 8
#define Dn 48
#define Fn 1536
#define GRN_EPS 1e-6f
#define LN_EPS 1e-5f

// ---------------- scratch (device globals; no allocations) ----------------
__device__ float g_ada[(size_t)Bn * Cn * NQ];      // GRN(query) channel-major
__device__ float g_q[(size_t)Bn * NQ * Cn];        // q rows (B,Nq,C)
__device__ float g_k[(size_t)Bn * NK * Cn];        // k rows (B,Nk,C)
__device__ float g_v[(size_t)Bn * NK * Cn];        // v rows (B,Nk,C)
__device__ float g_attn[(size_t)Bn * NQ * Cn];     // attention output rows (B,Nq,C)
__device__ float g_working[(size_t)Bn * Cn * NQ];  // residual stream, channel-major
__device__ float g_normed[(size_t)Bn * Cn * NQ];   // GRN(working), channel-major
__device__ float g_h[(size_t)Bn * NQ * Fn];        // FFN hidden (B,Nq,F)
__device__ float g_kv[(size_t)Bn * Hn * Dn * Dn];
__device__ float g_ksum[(size_t)Bn * Hn * Dn];
__device__ float g_gx[(size_t)Bn * Cn];
__device__ float g_meanc[Bn];

// ---------------- GRN ----------------
// gx[b,c] = sqrt(sum_hw x^2)
__global__ void grn_reduce_kernel(const float* __restrict__ x, float* __restrict__ gx, int N) {
    int bc = blockIdx.x;
    const float* p = x + (size_t)bc * N;
    float s = 0.f;
    for (int i = threadIdx.x; i < N; i += 256) {
        float v = p[i];
        s += v * v;
    }
    __shared__ float red[256];
    red[threadIdx.x] = s;
    __syncthreads();
    for (int st = 128; st > 0; st >>= 1) {
        if (threadIdx.x < st) red[threadIdx.x] += red[threadIdx.x + st];
        __syncthreads();
    }
    if (threadIdx.x == 0) gx[bc] = sqrtf(red[0]);
}

// meanc[b] = mean_c gx[b,c] + eps
__global__ void grn_mean_kernel(const float* __restrict__ gx, float* __restrict__ meanc) {
    int b = blockIdx.x;
    int t = threadIdx.x;  // 128
    float s = 0.f;
    for (int c = t; c < Cn; c += 128) s += gx[b * Cn + c];
    __shared__ float red[128];
    red[t] = s;
    __syncthreads();
    for (int st = 64; st > 0; st >>= 1) {
        if (t < st) red[t] += red[t + st];
        __syncthreads();
    }
    if (t == 0) meanc[b] = red[0] * (1.f / (float)Cn) + GRN_EPS;
}

// out = (1+gamma_c)*(x*nx) + beta_c + x   with nx = gx[b,c]/meanc[b]
__global__ void grn_apply_kernel(const float* __restrict__ x, const float* __restrict__ gx,
                                 const float* __restrict__ meanc,
                                 const float* __restrict__ gamma, const float* __restrict__ beta,
                                 float* __restrict__ out, int N) {
    size_t total = (size_t)Bn * Cn * N;
    size_t stride = (size_t)gridDim.x * blockDim.x;
    for (size_t i = (size_t)blockIdx.x * blockDim.x + threadIdx.x; i < total; i += stride) {
        size_t bc = i / (size_t)N;
        int c = (int)(bc % Cn);
        int b = (int)(bc / Cn);
        float nx = gx[bc] / meanc[b];
        float v = x[i];
        out[i] = (1.f + gamma[c]) * (v * nx) + beta[c] + v;
    }
}

// ---------------- GEMM: channel-major A ----------------
// Y[b,n,co] = sum_ci X[b,ci,n] * W[co,ci] + bias[co];  act 0=none, 1=silu
// grid (N/64, Cout/64, B), block 256
__global__ void gemm_cmA_kernel(const float* __restrict__ X, const float* __restrict__ W,
                                const float* __restrict__ bias, float* __restrict__ Y,
                                int N, int Cin, int Cout, int act) {
    int b = blockIdx.z;
    int n0 = blockIdx.x * 64, c0 = blockIdx.y * 64;
    __shared__ float As[16][65];  // [k][n]
    __shared__ float Bs[16][65];  // [k][co]
    int tid = threadIdx.x;
    int tc = tid & 15, tn = tid >> 4;  // out coalesced along co (row-major out)
    float acc[4][4] = {};
    const float* Xb = X + (size_t)b * Cin * N;
    for (int k0 = 0; k0 < Cin; k0 += 16) {
        for (int i = tid; i < 16 * 64; i += 256) {
            int kk = i >> 6, nn = i & 63;
            As[kk][nn] = Xb[(size_t)(k0 + kk) * N + n0 + nn];
        }
        for (int i = tid; i < 16 * 64; i += 256) {
            int cc = i >> 4, kk = i & 15;
            Bs[kk][cc] = W[(size_t)(c0 + cc) * Cin + k0 + kk];
        }
        __syncthreads();
#pragma unroll
        for (int kk = 0; kk < 16; kk++) {
            float a[4], w4[4];
#pragma unroll
            for (int i = 0; i < 4; i++) a[i] = As[kk][tn + i * 16];
#pragma unroll
            for (int j = 0; j < 4; j++) w4[j] = Bs[kk][tc + j * 16];
#pragma unroll
            for (int i = 0; i < 4; i++)
#pragma unroll
                for (int j = 0; j < 4; j++) acc[i][j] += a[i] * w4[j];
        }
        __syncthreads();
    }
    float* Yb = Y + (size_t)b * N * Cout;
#pragma unroll
    for (int i = 0; i < 4; i++) {
        int n = n0 + tn + i * 16;
#pragma unroll
        for (int j = 0; j < 4; j++) {
            int co = c0 + tc + j * 16;
            float val = acc[i][j] + bias[co];
            if (act == 1) val = val / (1.f + expf(-val));  // silu
            Yb[(size_t)n * Cout + co] = val;
        }
    }
}

// ---------------- GEMM: row-major A, channel-major out with fused epilogue ----------------
// val[b,n,co] = sum_f X[b,n,f]*W[co,f] + bias[co]
// mode 0: out[b,co,n] = resid1[b,co,n] + val*scal1[co]                       (Wo + attn residual)
// mode 1: out[b,co,n] = resid1 + (resid2 + val*scal1[co]) * scal2[co]        (FFN2 + final)
__global__ void gemm_rmA_kernel(const float* __restrict__ X, const float* __restrict__ W,
                                const float* __restrict__ bias,
                                const float* __restrict__ resid1, const float* __restrict__ resid2,
                                const float* __restrict__ scal1, const float* __restrict__ scal2,
                                float* __restrict__ out, int N, int F, int Cout, int mode) {
    int b = blockIdx.z;
    int n0 = blockIdx.x * 64, c0 = blockIdx.y * 64;
    __shared__ float As[16][65];  // [k][n]
    __shared__ float Bs[16][65];  // [k][co]
    int tid = threadIdx.x;
    int tn = tid & 15, tc = tid >> 4;  // out coalesced along n (channel-major out)
    float acc[4][4] = {};
    const float* Xb = X + (size_t)b * N * F;
    for (int k0 = 0; k0 < F; k0 += 16) {
        for (int i = tid; i < 16 * 64; i += 256) {
            int nn = i >> 4, kk = i & 15;
            As[kk][nn] = Xb[(size_t)(n0 + nn) * F + k0 + kk];
        }
        for (int i = tid; i < 16 * 64; i += 256) {
            int cc = i >> 4, kk = i & 15;
            Bs[kk][cc] = W[(size_t)(c0 + cc) * F + k0 + kk];
        }
        __syncthreads();
#pragma unroll
        for (int kk = 0; kk < 16; kk++) {
            float a[4], w4[4];
#pragma unroll
            for (int i = 0; i < 4; i++) a[i] = As[kk][tn + i * 16];
#pragma unroll
            for (int j = 0; j < 4; j++) w4[j] = Bs[kk][tc + j * 16];
#pragma unroll
            for (int i = 0; i < 4; i++)
#pragma unroll
                for (int j = 0; j < 4; j++) acc[i][j] += a[i] * w4[j];
        }
        __syncthreads();
    }
#pragma unroll
    for (int j = 0; j < 4; j++) {
        int co = c0 + tc + j * 16;
        float bv = bias[co];
        float s1 = scal1[co];
        float s2 = (mode == 1) ? scal2[co] : 0.f;
#pragma unroll
        for (int i = 0; i < 4; i++) {
            int n = n0 + tn + i * 16;
            size_t idx = ((size_t)b * Cout + co) * (size_t)N + n;
            float val = acc[i][j] + bv;
            if (mode == 0)
                out[idx] = resid1[idx] + val * s1;
            else
                out[idx] = resid1[idx] + (resid2[idx] + val * s1) * s2;
        }
    }
}

// ---------------- LayerNorm + elu+1 (in place on (rows, C)) ----------------
__global__ void ln_elu_kernel(float* __restrict__ x, const float* __restrict__ w,
                              const float* __restrict__ bvec) {
    int r = blockIdx.x;
    float* p = x + (size_t)r * Cn;
    int t = threadIdx.x;  // 128
    float v0 = p[t], v1 = p[t + 128], v2 = p[t + 256];
    float s = v0 + v1 + v2;
    float s2 = v0 * v0 + v1 * v1 + v2 * v2;
    __shared__ float red[128];
    red[t] = s;
    __syncthreads();
    for (int st = 64; st > 0; st >>= 1) {
        if (t < st) red[t] += red[t + st];
        __syncthreads();
    }
    float mu = red[0] * (1.f / (float)Cn);
    __syncthreads();
    red[t] = s2;
    __syncthreads();
    for (int st = 64; st > 0; st >>= 1) {
        if (t < st) red[t] += red[t + st];
        __syncthreads();
    }
    float var = red[0] * (1.f / (float)Cn) - mu * mu;
    float inv = rsqrtf(var + LN_EPS);
    float y;
    y = (v0 - mu) * inv * w[t] + bvec[t];
    p[t] = (y > 0.f) ? y + 1.f : expf(y);
    y = (v1 - mu) * inv * w[t + 128] + bvec[t + 128];
    p[t + 128] = (y > 0.f) ? y + 1.f : expf(y);
    y = (v2 - mu) * inv * w[t + 256] + bvec[t + 256];
    p[t + 256] = (y > 0.f) ? y + 1.f : expf(y);
}

// ---------------- kv_sum + k_sum per (b,h) ----------------
// kv[d,e] = sum_n k[b,n,h*D+d]*v[b,n,h*D+e];  ksum[d] = sum_n k[...]
__global__ void kv_kernel(const float* __restrict__ k, const float* __restrict__ v,
                          float* __restrict__ kv, float* __restrict__ ksum) {
    int bh = blockIdx.x;
    int b = bh / Hn, h = bh % Hn;
    __shared__ float ks[32][Dn];
    __shared__ float vs[32][Dn];
    int tid = threadIdx.x;  // 256
    float acc[9] = {};      // 9*256 == 48*48
    float ksacc = 0.f;
    for (int n0 = 0; n0 < NK; n0 += 32) {
        for (int i = tid; i < 32 * Dn; i += 256) {
            int nn = i / Dn, dd = i % Dn;
            size_t base = ((size_t)b * NK + n0 + nn) * Cn + h * Dn + dd;
            ks[nn][dd] = k[base];
            vs[nn][dd] = v[base];
        }
        __syncthreads();
#pragma unroll 4
        for (int nn = 0; nn < 32; nn++) {
#pragma unroll
            for (int o = 0; o < 9; o++) {
                int idx = tid + o * 256;
                int dd = idx / Dn, ee = idx % Dn;
                acc[o] += ks[nn][dd] * vs[nn][ee];
            }
            if (tid < Dn) ksacc += ks[nn][tid];
        }
        __syncthreads();
    }
#pragma unroll
    for (int o = 0; o < 9; o++) kv[(size_t)bh * Dn * Dn + tid + o * 256] = acc[o];
    if (tid < Dn) ksum[bh * Dn + tid] = ksacc;
}

// ---------------- attention: num/den ----------------
// attn[b,n,h*D+e] = (sum_d q[b,n,h*D+d]*kv[d,e]) / (sum_d q*ksum[d] + 1e-8)
__global__ void attn_kernel(const float* __restrict__ q, const float* __restrict__ kv,
                            const float* __restrict__ ksum, float* __restrict__ attn) {
    int bh = blockIdx.y;
    int b = bh / Hn, h = bh % Hn;
    int n0 = blockIdx.x * 64;
    __shared__ float kvs[Dn][Dn];
    __shared__ float kss[Dn];
    __shared__ float qs[64][Dn];
    __shared__ float dens[64];
    int tid = threadIdx.x;  // 256
    for (int i = tid; i < Dn * Dn; i += 256) kvs[i / Dn][i % Dn] = kv[(size_t)bh * Dn * Dn + i];
    if (tid < Dn) kss[tid] = ksum[bh * Dn + tid];
    for (int i = tid; i < 64 * Dn; i += 256) {
        int nn = i / Dn, dd = i % Dn;
        qs[nn][dd] = q[((size_t)b * NQ + n0 + nn) * Cn + h * Dn + dd];
    }
    __syncthreads();
    if (tid < 64) {
        float den = 0.f;
#pragma unroll
        for (int dd = 0; dd < Dn; dd++) den += qs[tid][dd] * kss[dd];
        dens[tid] = den + 1e-8f;
    }
    __syncthreads();
#pragma unroll
    for (int o = 0; o < 12; o++) {  // 12*256 == 64*48
        int idx = tid + o * 256;
        int nn = idx / Dn, ee = idx % Dn;
        float sacc = 0.f;
#pragma unroll
        for (int dd = 0; dd < Dn; dd++) sacc += qs[nn][dd] * kvs[dd][ee];
        attn[((size_t)b * NQ + n0 + nn) * Cn + h * Dn + ee] = sacc / dens[nn];
    }
}

// ---------------- host launch ----------------
extern "C" void kernel_launch(void* const* d_in, const int* in_sizes, int n_in,
                              void* d_out, int out_size) {
    const float* query = (const float*)d_in[0];
    const float* key = (const float*)d_in[1];
    const float* value = (const float*)d_in[2];
    const float* ada_gamma = (const float*)d_in[3];
    const float* ada_beta = (const float*)d_in[4];
    const float* Wq = (const float*)d_in[5];
    const float* bq = (const float*)d_in[6];
    const float* Wk = (const float*)d_in[7];
    const float* bk = (const float*)d_in[8];
    const float* Wv = (const float*)d_in[9];
    const float* bv = (const float*)d_in[10];
    const float* Wo = (const float*)d_in[11];
    const float* bo = (const float*)d_in[12];
    const float* lnq_w = (const float*)d_in[13];
    const float* lnq_b = (const float*)d_in[14];
    const float* lnk_w = (const float*)d_in[15];
    const float* lnk_b = (const float*)d_in[16];
    const float* attn_scalar = (const float*)d_in[17];
    const float* ffn_gamma = (const float*)d_in[18];
    const float* ffn_beta = (const float*)d_in[19];
    const float* W1 = (const float*)d_in[20];
    const float* b1 = (const float*)d_in[21];
    const float* W2 = (const float*)d_in[22];
    const float* b2 = (const float*)d_in[23];
    const float* ffn_scalar = (const float*)d_in[24];
    const float* final_scalar = (const float*)d_in[25];
    float* out = (float*)d_out;

    float *ada, *q, *k, *v, *attn, *working, *normed, *hbuf, *kv, *ksum, *gx, *meanc;
    cudaGetSymbolAddress((void**)&ada, g_ada);
    cudaGetSymbolAddress((void**)&q, g_q);
    cudaGetSymbolAddress((void**)&k, g_k);
    cudaGetSymbolAddress((void**)&v, g_v);
    cudaGetSymbolAddress((void**)&attn, g_attn);
    cudaGetSymbolAddress((void**)&working, g_working);
    cudaGetSymbolAddress((void**)&normed, g_normed);
    cudaGetSymbolAddress((void**)&hbuf, g_h);
    cudaGetSymbolAddress((void**)&kv, g_kv);
    cudaGetSymbolAddress((void**)&ksum, g_ksum);
    cudaGetSymbolAddress((void**)&gx, g_gx);
    cudaGetSymbolAddress((void**)&meanc, g_meanc);

    // 1) GRN on query -> ada
    grn_reduce_kernel<<<Bn * Cn, 256>>>(query, gx, NQ);
    grn_mean_kernel<<<Bn, 128>>>(gx, meanc);
    grn_apply_kernel<<<4096, 256>>>(query, gx, meanc, ada_gamma, ada_beta, ada, NQ);

    // 2) projections
    gemm_cmA_kernel<<<dim3(NQ / 64, Cn / 64, Bn), 256>>>(ada, Wq, bq, q, NQ, Cn, Cn, 0);
    gemm_cmA_kernel<<<dim3(NK / 64, Cn / 64, Bn), 256>>>(key, Wk, bk, k, NK, Cn, Cn, 0);
    gemm_cmA_kernel<<<dim3(NK / 64, Cn / 64, Bn), 256>>>(value, Wv, bv, v, NK, Cn, Cn, 0);

    // 3) LN + elu+1 (in place)
    ln_elu_kernel<<<Bn * NQ, 128>>>(q, lnq_w, lnq_b);
    ln_elu_kernel<<<Bn * NK, 128>>>(k, lnk_w, lnk_b);

    // 4) kv_sum, k_sum
    kv_kernel<<<Bn * Hn, 256>>>(k, v, kv, ksum);

    // 5) linear attention num/den
    attn_kernel<<<dim3(NQ / 64, Bn * Hn), 256>>>(q, kv, ksum, attn);

    // 6) Wo projection + attn residual -> working (channel-major)
    gemm_rmA_kernel<<<dim3(NQ / 64, Cn / 64, Bn), 256>>>(attn, Wo, bo, query, nullptr,
                                                         attn_scalar, nullptr, working,
                                                         NQ, Cn, Cn, 0);

    // 7) GRN on working -> normed
    grn_reduce_kernel<<<Bn * Cn, 256>>>(working, gx, NQ);
    grn_mean_kernel<<<Bn, 128>>>(gx, meanc);
    grn_apply_kernel<<<4096, 256>>>(working, gx, meanc, ffn_gamma, ffn_beta, normed, NQ);

    // 8) FFN1 (+silu) -> h
    gemm_cmA_kernel<<<dim3(NQ / 64, Fn / 64, Bn), 256>>>(normed, W1, b1, hbuf, NQ, Cn, Fn, 1);

    // 9) FFN2 + ffn residual + final residual -> out
    gemm_rmA_kernel<<<dim3(NQ / 64, Cn / 64, Bn), 256>>>(hbuf, W2, b2, query, working,
                                                         ffn_scalar, final_scalar, out,
                                                         NQ, Fn, Cn, 1);
}

// round 3
// speedup vs baseline: 2.3048x; 2.3048x over previous
#include <cuda_runtime.h>
#include <math.h>
#include <stdint.h>

// Problem constants
#define Bn 8
#define Cn 384
#define NQ 4096
#define NK 1024
#define Hn 8
#define Dn 48
#define Fn 1536
#define GRN_EPS 1e-6f
#define LN_EPS 1e-5f

// GEMM tiling
#define KS 16
#define BM 128
#define BN 128
#define PITCH 136  // 136 % 32 == 8 -> conflict-free fragment loads

// ---------------- scratch (device globals; no allocations) ----------------
__device__ float g_ada[(size_t)Bn * Cn * NQ];      // GRN(query) channel-major
__device__ float g_q[(size_t)Bn * NQ * Cn];        // q rows (B,Nq,C)
__device__ float g_k[(size_t)Bn * NK * Cn];        // k rows (B,Nk,C)
__device__ float g_v[(size_t)Bn * NK * Cn];        // v rows (B,Nk,C)
__device__ float g_attn[(size_t)Bn * NQ * Cn];     // attention output rows (B,Nq,C)
__device__ float g_working[(size_t)Bn * Cn * NQ];  // residual stream, channel-major
__device__ float g_normed[(size_t)Bn * Cn * NQ];   // GRN(working), channel-major
__device__ float g_h[(size_t)Bn * NQ * Fn];        // FFN hidden (B,Nq,F)
__device__ float g_kv[(size_t)Bn * Hn * Dn * Dn];
__device__ float g_ksum[(size_t)Bn * Hn * Dn];
__device__ float g_gx[(size_t)Bn * Cn];
__device__ float g_meanc[Bn];

// ---------------- tf32 helpers ----------------
__device__ __forceinline__ uint32_t f2tf32(float x) {
    uint32_t r;
    asm("cvt.rna.tf32.f32 %0, %1;" : "=r"(r) : "f"(x));
    return r;
}

__device__ __forceinline__ void mma8(float* c, uint32_t a0, uint32_t a1, uint32_t a2,
                                     uint32_t a3, uint32_t b0, uint32_t b1) {
    asm volatile(
        "mma.sync.aligned.m16n8k8.row.col.f32.tf32.tf32.f32 "
        "{%0,%1,%2,%3},{%4,%5,%6,%7},{%8,%9},{%0,%1,%2,%3};"
        : "+f"(c[0]), "+f"(c[1]), "+f"(c[2]), "+f"(c[3])
        : "r"(a0), "r"(a1), "r"(a2), "r"(a3), "r"(b0), "r"(b1));
}

// ---------------- GRN ----------------
__global__ void grn_reduce_kernel(const float* __restrict__ x, float* __restrict__ gx, int N) {
    int bc = blockIdx.x;
    const float* p = x + (size_t)bc * N;
    float s = 0.f;
    for (int i = threadIdx.x; i < N; i += 256) {
        float v = p[i];
        s += v * v;
    }
    __shared__ float red[256];
    red[threadIdx.x] = s;
    __syncthreads();
    for (int st = 128; st > 0; st >>= 1) {
        if (threadIdx.x < st) red[threadIdx.x] += red[threadIdx.x + st];
        __syncthreads();
    }
    if (threadIdx.x == 0) gx[bc] = sqrtf(red[0]);
}

__global__ void grn_mean_kernel(const float* __restrict__ gx, float* __restrict__ meanc) {
    int b = blockIdx.x;
    int t = threadIdx.x;  // 128
    float s = 0.f;
    for (int c = t; c < Cn; c += 128) s += gx[b * Cn + c];
    __shared__ float red[128];
    red[t] = s;
    __syncthreads();
    for (int st = 64; st > 0; st >>= 1) {
        if (t < st) red[t] += red[t + st];
        __syncthreads();
    }
    if (t == 0) meanc[b] = red[0] * (1.f / (float)Cn) + GRN_EPS;
}

__global__ void grn_apply_kernel(const float* __restrict__ x, const float* __restrict__ gx,
                                 const float* __restrict__ meanc,
                                 const float* __restrict__ gamma, const float* __restrict__ beta,
                                 float* __restrict__ out, int N) {
    size_t total = (size_t)Bn * Cn * N;
    size_t stride = (size_t)gridDim.x * blockDim.x;
    for (size_t i = (size_t)blockIdx.x * blockDim.x + threadIdx.x; i < total; i += stride) {
        size_t bc = i / (size_t)N;
        int c = (int)(bc % Cn);
        int b = (int)(bc / Cn);
        float nx = gx[bc] / meanc[b];
        float v = x[i];
        out[i] = (1.f + gamma[c]) * (v * nx) + beta[c] + v;
    }
}

// ---------------- tensor-core GEMM: channel-major A ----------------
// Y[b,m,co] = sum_k X[b,k,m] * W[co,k] + bias[co];  act 1 = silu
// grid (N/128, Cout/128, B), block 256
__global__ void gemm_cmA_tc(const float* __restrict__ X, const float* __restrict__ W,
                            const float* __restrict__ bias, float* __restrict__ Y,
                            int N, int Cin, int Cout, int act) {
    int b = blockIdx.z;
    int m0 = blockIdx.x * BM;
    int c0 = blockIdx.y * BN;
    __shared__ uint32_t As[KS][PITCH];
    __shared__ uint32_t Bs[KS][PITCH];
    int tid = threadIdx.x;
    int warp = tid >> 5, lane = tid & 31;
    int g = lane >> 2, lq = lane & 3;
    int wm = (warp >> 2) * 64;
    int wn = (warp & 3) * 32;
    float acc[4][4][4] = {};
    const float* Xb = X + (size_t)b * Cin * N;

    for (int k0 = 0; k0 < Cin; k0 += KS) {
        // A slab: 16 x 128, coalesced along m
        {
            int r = tid >> 5;
            int col = (tid & 31) * 4;
#pragma unroll
            for (int p = 0; p < 2; p++) {
                float4 v = *(const float4*)(Xb + (size_t)(k0 + r + p * 8) * N + m0 + col);
                uint32_t* dst = &As[r + p * 8][col];
                dst[0] = f2tf32(v.x); dst[1] = f2tf32(v.y);
                dst[2] = f2tf32(v.z); dst[3] = f2tf32(v.w);
            }
        }
        // B slab: W[co][k] -> Bs[k][co]
        {
            int cc = tid & 127;
            int kc = tid >> 7;
#pragma unroll
            for (int p = 0; p < 2; p++) {
                int kk = (kc + p * 2) * 4;
                float4 v = *(const float4*)(W + (size_t)(c0 + cc) * Cin + k0 + kk);
                Bs[kk + 0][cc] = f2tf32(v.x); Bs[kk + 1][cc] = f2tf32(v.y);
                Bs[kk + 2][cc] = f2tf32(v.z); Bs[kk + 3][cc] = f2tf32(v.w);
            }
        }
        __syncthreads();
#pragma unroll
        for (int ks = 0; ks < KS; ks += 8) {
            uint32_t af[4][4], bf[4][2];
#pragma unroll
            for (int mf = 0; mf < 4; mf++) {
                int m = wm + mf * 16 + g;
                af[mf][0] = As[ks + lq][m];
                af[mf][1] = As[ks + lq][m + 8];
                af[mf][2] = As[ks + lq + 4][m];
                af[mf][3] = As[ks + lq + 4][m + 8];
            }
#pragma unroll
            for (int nf = 0; nf < 4; nf++) {
                int c = wn + nf * 8 + g;
                bf[nf][0] = Bs[ks + lq][c];
                bf[nf][1] = Bs[ks + lq + 4][c];
            }
#pragma unroll
            for (int mf = 0; mf < 4; mf++)
#pragma unroll
                for (int nf = 0; nf < 4; nf++)
                    mma8(acc[mf][nf], af[mf][0], af[mf][1], af[mf][2], af[mf][3],
                         bf[nf][0], bf[nf][1]);
        }
        __syncthreads();
    }

    float* Yb = Y + (size_t)b * N * Cout;
#pragma unroll
    for (int mf = 0; mf < 4; mf++) {
#pragma unroll
        for (int nf = 0; nf < 4; nf++) {
            int co = c0 + wn + nf * 8 + lq * 2;
            float b0v = bias[co], b1v = bias[co + 1];
#pragma unroll
            for (int hr = 0; hr < 2; hr++) {
                int m = m0 + wm + mf * 16 + g + hr * 8;
                float v0 = acc[mf][nf][hr * 2 + 0] + b0v;
                float v1 = acc[mf][nf][hr * 2 + 1] + b1v;
                if (act == 1) {
                    v0 = v0 / (1.f + expf(-v0));
                    v1 = v1 / (1.f + expf(-v1));
                }
                *(float2*)(Yb + (size_t)m * Cout + co) = make_float2(v0, v1);
            }
        }
    }
}

// ---------------- tensor-core GEMM: row-major A, channel-major fused out ----------------
// val[b,m,co] = sum_k X[b,m,k]*W[co,k] + bias[co]
// mode 0: out[b,co,m] = resid1 + val*s1[co]
// mode 1: out[b,co,m] = resid1 + (resid2 + val*s1[co]) * s2[co]
__global__ void gemm_rmA_tc(const float* __restrict__ X, const float* __restrict__ W,
                            const float* __restrict__ bias,
                            const float* __restrict__ resid1, const float* __restrict__ resid2,
                            const float* __restrict__ scal1, const float* __restrict__ scal2,
                            float* __restrict__ out, int N, int F, int Cout, int mode) {
    int b = blockIdx.z;
    int m0 = blockIdx.x * BM;
    int c0 = blockIdx.y * BN;
    __shared__ uint32_t As[KS][PITCH];
    __shared__ uint32_t Bs[KS][PITCH];
    int tid = threadIdx.x;
    int warp = tid >> 5, lane = tid & 31;
    int g = lane >> 2, lq = lane & 3;
    int wm = (warp >> 2) * 64;
    int wn = (warp & 3) * 32;
    float acc[4][4][4] = {};
    const float* Xb = X + (size_t)b * N * F;

    for (int k0 = 0; k0 < F; k0 += KS) {
        // A slab: X[m][k] -> As[k][m]
        {
            int nn = tid & 127;
            int kc = tid >> 7;
#pragma unroll
            for (int p = 0; p < 2; p++) {
                int kk = (kc + p * 2) * 4;
                float4 v = *(const float4*)(Xb + (size_t)(m0 + nn) * F + k0 + kk);
                As[kk + 0][nn] = f2tf32(v.x); As[kk + 1][nn] = f2tf32(v.y);
                As[kk + 2][nn] = f2tf32(v.z); As[kk + 3][nn] = f2tf32(v.w);
            }
        }
        // B slab: W[co][k] -> Bs[k][co]
        {
            int cc = tid & 127;
            int kc = tid >> 7;
#pragma unroll
            for (int p = 0; p < 2; p++) {
                int kk = (kc + p * 2) * 4;
                float4 v = *(const float4*)(W + (size_t)(c0 + cc) * F + k0 + kk);
                Bs[kk + 0][cc] = f2tf32(v.x); Bs[kk + 1][cc] = f2tf32(v.y);
                Bs[kk + 2][cc] = f2tf32(v.z); Bs[kk + 3][cc] = f2tf32(v.w);
            }
        }
        __syncthreads();
#pragma unroll
        for (int ks = 0; ks < KS; ks += 8) {
            uint32_t af[4][4], bf[4][2];
#pragma unroll
            for (int mf = 0; mf < 4; mf++) {
                int m = wm + mf * 16 + g;
                af[mf][0] = As[ks + lq][m];
                af[mf][1] = As[ks + lq][m + 8];
                af[mf][2] = As[ks + lq + 4][m];
                af[mf][3] = As[ks + lq + 4][m + 8];
            }
#pragma unroll
            for (int nf = 0; nf < 4; nf++) {
                int c = wn + nf * 8 + g;
                bf[nf][0] = Bs[ks + lq][c];
                bf[nf][1] = Bs[ks + lq + 4][c];
            }
#pragma unroll
            for (int mf = 0; mf < 4; mf++)
#pragma unroll
                for (int nf = 0; nf < 4; nf++)
                    mma8(acc[mf][nf], af[mf][0], af[mf][1], af[mf][2], af[mf][3],
                         bf[nf][0], bf[nf][1]);
        }
        __syncthreads();
    }

#pragma unroll
    for (int nf = 0; nf < 4; nf++) {
#pragma unroll
        for (int cj = 0; cj < 2; cj++) {
            int co = c0 + wn + nf * 8 + lq * 2 + cj;
            float bv = bias[co];
            float s1 = scal1[co];
            float s2 = (mode == 1) ? scal2[co] : 0.f;
#pragma unroll
            for (int mf = 0; mf < 4; mf++) {
#pragma unroll
                for (int hr = 0; hr < 2; hr++) {
                    int m = m0 + wm + mf * 16 + g + hr * 8;
                    size_t idx = ((size_t)b * Cout + co) * (size_t)N + m;
                    float val = acc[mf][nf][hr * 2 + cj] + bv;
                    if (mode == 0)
                        out[idx] = resid1[idx] + val * s1;
                    else
                        out[idx] = resid1[idx] + (resid2[idx] + val * s1) * s2;
                }
            }
        }
    }
}

// ---------------- LayerNorm + elu+1 (in place on (rows, C)) ----------------
__global__ void ln_elu_kernel(float* __restrict__ x, const float* __restrict__ w,
                              const float* __restrict__ bvec) {
    int r = blockIdx.x;
    float* p = x + (size_t)r * Cn;
    int t = threadIdx.x;  // 128
    float v0 = p[t], v1 = p[t + 128], v2 = p[t + 256];
    float s = v0 + v1 + v2;
    float s2 = v0 * v0 + v1 * v1 + v2 * v2;
    __shared__ float red[128];
    red[t] = s;
    __syncthreads();
    for (int st = 64; st > 0; st >>= 1) {
        if (t < st) red[t] += red[t + st];
        __syncthreads();
    }
    float mu = red[0] * (1.f / (float)Cn);
    __syncthreads();
    red[t] = s2;
    __syncthreads();
    for (int st = 64; st > 0; st >>= 1) {
        if (t < st) red[t] += red[t + st];
        __syncthreads();
    }
    float var = red[0] * (1.f / (float)Cn) - mu * mu;
    float inv = rsqrtf(var + LN_EPS);
    float y;
    y = (v0 - mu) * inv * w[t] + bvec[t];
    p[t] = (y > 0.f) ? y + 1.f : expf(y);
    y = (v1 - mu) * inv * w[t + 128] + bvec[t + 128];
    p[t + 128] = (y > 0.f) ? y + 1.f : expf(y);
    y = (v2 - mu) * inv * w[t + 256] + bvec[t + 256];
    p[t + 256] = (y > 0.f) ? y + 1.f : expf(y);
}

// ---------------- kv_sum + k_sum per (b,h) ----------------
__global__ void kv_kernel(const float* __restrict__ k, const float* __restrict__ v,
                          float* __restrict__ kv, float* __restrict__ ksum) {
    int bh = blockIdx.x;
    int b = bh / Hn, h = bh % Hn;
    __shared__ float ks[32][Dn];
    __shared__ float vs[32][Dn];
    int tid = threadIdx.x;  // 256
    float acc[9] = {};
    float ksacc = 0.f;
    for (int n0 = 0; n0 < NK; n0 += 32) {
        for (int i = tid; i < 32 * Dn; i += 256) {
            int nn = i / Dn, dd = i % Dn;
            size_t base = ((size_t)b * NK + n0 + nn) * Cn + h * Dn + dd;
            ks[nn][dd] = k[base];
            vs[nn][dd] = v[base];
        }
        __syncthreads();
#pragma unroll 4
        for (int nn = 0; nn < 32; nn++) {
#pragma unroll
            for (int o = 0; o < 9; o++) {
                int idx = tid + o * 256;
                int dd = idx / Dn, ee = idx % Dn;
                acc[o] += ks[nn][dd] * vs[nn][ee];
            }
            if (tid < Dn) ksacc += ks[nn][tid];
        }
        __syncthreads();
    }
#pragma unroll
    for (int o = 0; o < 9; o++) kv[(size_t)bh * Dn * Dn + tid + o * 256] = acc[o];
    if (tid < Dn) ksum[bh * Dn + tid] = ksacc;
}

// ---------------- attention: num/den ----------------
__global__ void attn_kernel(const float* __restrict__ q, const float* __restrict__ kv,
                            const float* __restrict__ ksum, float* __restrict__ attn) {
    int bh = blockIdx.y;
    int b = bh / Hn, h = bh % Hn;
    int n0 = blockIdx.x * 64;
    __shared__ float kvs[Dn][Dn];
    __shared__ float kss[Dn];
    __shared__ float qs[64][Dn];
    __shared__ float dens[64];
    int tid = threadIdx.x;  // 256
    for (int i = tid; i < Dn * Dn; i += 256) kvs[i / Dn][i % Dn] = kv[(size_t)bh * Dn * Dn + i];
    if (tid < Dn) kss[tid] = ksum[bh * Dn + tid];
    for (int i = tid; i < 64 * Dn; i += 256) {
        int nn = i / Dn, dd = i % Dn;
        qs[nn][dd] = q[((size_t)b * NQ + n0 + nn) * Cn + h * Dn + dd];
    }
    __syncthreads();
    if (tid < 64) {
        float den = 0.f;
#pragma unroll
        for (int dd = 0; dd < Dn; dd++) den += qs[tid][dd] * kss[dd];
        dens[tid] = den + 1e-8f;
    }
    __syncthreads();
#pragma unroll
    for (int o = 0; o < 12; o++) {
        int idx = tid + o * 256;
        int nn = idx / Dn, ee = idx % Dn;
        float sacc = 0.f;
#pragma unroll
        for (int dd = 0; dd < Dn; dd++) sacc += qs[nn][dd] * kvs[dd][ee];
        attn[((size_t)b * NQ + n0 + nn) * Cn + h * Dn + ee] = sacc / dens[nn];
    }
}

// ---------------- host launch ----------------
extern "C" void kernel_launch(void* const* d_in, const int* in_sizes, int n_in,
                              void* d_out, int out_size) {
    const float* query = (const float*)d_in[0];
    const float* key = (const float*)d_in[1];
    const float* value = (const float*)d_in[2];
    const float* ada_gamma = (const float*)d_in[3];
    const float* ada_beta = (const float*)d_in[4];
    const float* Wq = (const float*)d_in[5];
    const float* bq = (const float*)d_in[6];
    const float* Wk = (const float*)d_in[7];
    const float* bk = (const float*)d_in[8];
    const float* Wv = (const float*)d_in[9];
    const float* bv = (const float*)d_in[10];
    const float* Wo = (const float*)d_in[11];
    const float* bo = (const float*)d_in[12];
    const float* lnq_w = (const float*)d_in[13];
    const float* lnq_b = (const float*)d_in[14];
    const float* lnk_w = (const float*)d_in[15];
    const float* lnk_b = (const float*)d_in[16];
    const float* attn_scalar = (const float*)d_in[17];
    const float* ffn_gamma = (const float*)d_in[18];
    const float* ffn_beta = (const float*)d_in[19];
    const float* W1 = (const float*)d_in[20];
    const float* b1 = (const float*)d_in[21];
    const float* W2 = (const float*)d_in[22];
    const float* b2 = (const float*)d_in[23];
    const float* ffn_scalar = (const float*)d_in[24];
    const float* final_scalar = (const float*)d_in[25];
    float* out = (float*)d_out;

    float *ada, *q, *k, *v, *attn, *working, *normed, *hbuf, *kv, *ksum, *gx, *meanc;
    cudaGetSymbolAddress((void**)&ada, g_ada);
    cudaGetSymbolAddress((void**)&q, g_q);
    cudaGetSymbolAddress((void**)&k, g_k);
    cudaGetSymbolAddress((void**)&v, g_v);
    cudaGetSymbolAddress((void**)&attn, g_attn);
    cudaGetSymbolAddress((void**)&working, g_working);
    cudaGetSymbolAddress((void**)&normed, g_normed);
    cudaGetSymbolAddress((void**)&hbuf, g_h);
    cudaGetSymbolAddress((void**)&kv, g_kv);
    cudaGetSymbolAddress((void**)&ksum, g_ksum);
    cudaGetSymbolAddress((void**)&gx, g_gx);
    cudaGetSymbolAddress((void**)&meanc, g_meanc);

    // 1) GRN on query -> ada
    grn_reduce_kernel<<<Bn * Cn, 256>>>(query, gx, NQ);
    grn_mean_kernel<<<Bn, 128>>>(gx, meanc);
    grn_apply_kernel<<<4096, 256>>>(query, gx, meanc, ada_gamma, ada_beta, ada, NQ);

    // 2) projections (tensor core tf32)
    gemm_cmA_tc<<<dim3(NQ / BM, Cn / BN, Bn), 256>>>(ada, Wq, bq, q, NQ, Cn, Cn, 0);
    gemm_cmA_tc<<<dim3(NK / BM, Cn / BN, Bn), 256>>>(key, Wk, bk, k, NK, Cn, Cn, 0);
    gemm_cmA_tc<<<dim3(NK / BM, Cn / BN, Bn), 256>>>(value, Wv, bv, v, NK, Cn, Cn, 0);

    // 3) LN + elu+1 (in place)
    ln_elu_kernel<<<Bn * NQ, 128>>>(q, lnq_w, lnq_b);
    ln_elu_kernel<<<Bn * NK, 128>>>(k, lnk_w, lnk_b);

    // 4) kv_sum, k_sum
    kv_kernel<<<Bn * Hn, 256>>>(k, v, kv, ksum);

    // 5) linear attention num/den
    attn_kernel<<<dim3(NQ / 64, Bn * Hn), 256>>>(q, kv, ksum, attn);

    // 6) Wo projection + attn residual -> working (channel-major)
    gemm_rmA_tc<<<dim3(NQ / BM, Cn / BN, Bn), 256>>>(attn, Wo, bo, query, nullptr,
                                                     attn_scalar, nullptr, working,
                                                     NQ, Cn, Cn, 0);

    // 7) GRN on working -> normed
    grn_reduce_kernel<<<Bn * Cn, 256>>>(working, gx, NQ);
    grn_mean_kernel<<<Bn, 128>>>(gx, meanc);
    grn_apply_kernel<<<4096, 256>>>(working, gx, meanc, ffn_gamma, ffn_beta, normed, NQ);

    // 8) FFN1 (+silu) -> h
    gemm_cmA_tc<<<dim3(NQ / BM, Fn / BN, Bn), 256>>>(normed, W1, b1, hbuf, NQ, Cn, Fn, 1);

    // 9) FFN2 + ffn residual + final residual -> out
    gemm_rmA_tc<<<dim3(NQ / BM, Cn / BN, Bn), 256>>>(hbuf, W2, b2, query, working,
                                                     ffn_scalar, final_scalar, out,
                                                     NQ, Fn, Cn, 1);
}

// round 4
// speedup vs baseline: 3.4814x; 1.5105x over previous
#include <cuda_runtime.h>
#include <math.h>
#include <stdint.h>

// Problem constants
#define Bn 8
#define Cn 384
#define NQ 4096
#define NK 1024
#define Hn 8
#define Dn 48
#define Fn 1536
#define GRN_EPS 1e-6f
#define LN_EPS 1e-5f

// GEMM tiling
#define KS 16
#define BM 128
#define BN 128
#define PITCHA 136  // [k][m] rows: lq*136 mod 32 = lq*8 -> conflict-free
#define PITCHR 20   // [row][k] rows: g*20 mod 32 spans all banks -> conflict-free

// ---------------- scratch (device globals; no allocations) ----------------
__device__ float g_ada[(size_t)Bn * Cn * NQ];
__device__ float g_q[(size_t)Bn * NQ * Cn];
__device__ float g_k[(size_t)Bn * NK * Cn];
__device__ float g_v[(size_t)Bn * NK * Cn];
__device__ float g_attn[(size_t)Bn * NQ * Cn];
__device__ float g_working[(size_t)Bn * Cn * NQ];
__device__ float g_normed[(size_t)Bn * Cn * NQ];
__device__ float g_h[(size_t)Bn * NQ * Fn];
__device__ float g_kv[(size_t)Bn * Hn * Dn * Dn];
__device__ float g_ksum[(size_t)Bn * Hn * Dn];
__device__ float g_gx[(size_t)Bn * Cn];
__device__ float g_meanc[Bn];

// ---------------- helpers ----------------
__device__ __forceinline__ void cp_async16(void* smem_dst, const void* gsrc) {
    uint32_t s = (uint32_t)__cvta_generic_to_shared(smem_dst);
    asm volatile("cp.async.cg.shared.global [%0], [%1], 16;" ::"r"(s), "l"(gsrc));
}
__device__ __forceinline__ void cp_commit() { asm volatile("cp.async.commit_group;"); }
__device__ __forceinline__ void cp_wait1() { asm volatile("cp.async.wait_group 1;"); }
__device__ __forceinline__ void cp_wait0() { asm volatile("cp.async.wait_group 0;"); }

// raw fp32 bits fed as tf32 (HW truncates mantissa; RZ instead of RNA rounding)
__device__ __forceinline__ void mma8(float* c, float a0, float a1, float a2, float a3,
                                     float b0, float b1) {
    asm volatile(
        "mma.sync.aligned.m16n8k8.row.col.f32.tf32.tf32.f32 "
        "{%0,%1,%2,%3},{%4,%5,%6,%7},{%8,%9},{%0,%1,%2,%3};"
        : "+f"(c[0]), "+f"(c[1]), "+f"(c[2]), "+f"(c[3])
        : "r"(__float_as_uint(a0)), "r"(__float_as_uint(a1)), "r"(__float_as_uint(a2)),
          "r"(__float_as_uint(a3)), "r"(__float_as_uint(b0)), "r"(__float_as_uint(b1)));
}

// ---------------- GRN ----------------
__global__ void grn_reduce_kernel(const float* __restrict__ x, float* __restrict__ gx, int N) {
    int bc = blockIdx.x;
    const float4* p = (const float4*)(x + (size_t)bc * N);
    int n4 = N >> 2;
    float s = 0.f;
    for (int i = threadIdx.x; i < n4; i += 256) {
        float4 v = p[i];
        s += v.x * v.x + v.y * v.y + v.z * v.z + v.w * v.w;
    }
    __shared__ float red[256];
    red[threadIdx.x] = s;
    __syncthreads();
    for (int st = 128; st > 0; st >>= 1) {
        if (threadIdx.x < st) red[threadIdx.x] += red[threadIdx.x + st];
        __syncthreads();
    }
    if (threadIdx.x == 0) gx[bc] = sqrtf(red[0]);
}

__global__ void grn_mean_kernel(const float* __restrict__ gx, float* __restrict__ meanc) {
    int b = blockIdx.x;
    int t = threadIdx.x;  // 128
    float s = 0.f;
    for (int c = t; c < Cn; c += 128) s += gx[b * Cn + c];
    __shared__ float red[128];
    red[t] = s;
    __syncthreads();
    for (int st = 64; st > 0; st >>= 1) {
        if (t < st) red[t] += red[t + st];
        __syncthreads();
    }
    if (t == 0) meanc[b] = red[0] * (1.f / (float)Cn) + GRN_EPS;
}

// out = x*(1 + (1+gamma_c)*nx) + beta_c, vectorized float4; N = NQ fixed
__global__ void grn_apply_kernel(const float* __restrict__ x, const float* __restrict__ gx,
                                 const float* __restrict__ meanc,
                                 const float* __restrict__ gamma, const float* __restrict__ beta,
                                 float* __restrict__ out) {
    const int N4 = NQ >> 2;  // 1024
    size_t total = (size_t)Bn * Cn * N4;
    size_t stride = (size_t)gridDim.x * blockDim.x;
    const float4* x4 = (const float4*)x;
    float4* o4 = (float4*)out;
    for (size_t i = (size_t)blockIdx.x * blockDim.x + threadIdx.x; i < total; i += stride) {
        size_t bc = i >> 10;  // / N4
        int c = (int)(bc % Cn);
        int b = (int)(bc / Cn);
        float nx = gx[bc] / meanc[b];
        float sc = 1.f + (1.f + gamma[c]) * nx;
        float bt = beta[c];
        float4 v = x4[i];
        o4[i] = make_float4(v.x * sc + bt, v.y * sc + bt, v.z * sc + bt, v.w * sc + bt);
    }
}

// ---------------- tensor-core GEMM: channel-major A, cp.async double-buffered ----------------
// Y[b,m,co] = sum_k X[b,k,m] * W[co,k] + bias[co];  act 1 = silu
__global__ void gemm_cmA_tc(const float* __restrict__ X, const float* __restrict__ W,
                            const float* __restrict__ bias, float* __restrict__ Y,
                            int N, int Cin, int Cout, int act) {
    int b = blockIdx.z;
    int m0 = blockIdx.x * BM;
    int c0 = blockIdx.y * BN;
    __shared__ float As[2][KS][PITCHA];   // [k][m]
    __shared__ float Bs[2][BN][PITCHR];   // [co][k]
    int tid = threadIdx.x;
    int warp = tid >> 5, lane = tid & 31;
    int g = lane >> 2, lq = lane & 3;
    int wm = (warp >> 2) * 64;
    int wn = (warp & 3) * 32;
    float acc[4][4][4] = {};
    const float* Xb = X + (size_t)b * Cin * N;

    // chunk decomposition (per thread: 2 A-chunks, 2 B-chunks per slab)
    int a_k0 = tid >> 5, a_m = (tid & 31) << 2;          // +8 rows for second
    int b_c = tid >> 1, b_k = (tid & 1) << 3;            // 2 chunks of 8 floats? no:
    // A: 512 chunks: c -> k=c>>5, m=(c&31)*4 ; B: 512 chunks: c -> co=c>>2, k=(c&3)*4
    int nslab = Cin / KS;

#define LOAD_CM(slab, buf)                                                                  \
    {                                                                                       \
        int kk0 = (slab)*KS;                                                                \
        _Pragma("unroll") for (int p = 0; p < 2; p++) {                                     \
            int c = tid + p * 256;                                                          \
            int ak = c >> 5, am = (c & 31) << 2;                                            \
            cp_async16(&As[buf][ak][am], Xb + (size_t)(kk0 + ak) * N + m0 + am);            \
            int bc = c >> 2, bk = (c & 3) << 2;                                             \
            cp_async16(&Bs[buf][bc][bk], W + (size_t)(c0 + bc) * Cin + kk0 + bk);           \
        }                                                                                   \
        cp_commit();                                                                        \
    }

    LOAD_CM(0, 0);
    for (int s = 0; s < nslab; s++) {
        int buf = s & 1;
        if (s + 1 < nslab) {
            LOAD_CM(s + 1, buf ^ 1);
            cp_wait1();
        } else {
            cp_wait0();
        }
        __syncthreads();
#pragma unroll
        for (int ks = 0; ks < KS; ks += 8) {
            float af[4][4], bf[4][2];
#pragma unroll
            for (int mf = 0; mf < 4; mf++) {
                int m = wm + mf * 16 + g;
                af[mf][0] = As[buf][ks + lq][m];
                af[mf][1] = As[buf][ks + lq][m + 8];
                af[mf][2] = As[buf][ks + lq + 4][m];
                af[mf][3] = As[buf][ks + lq + 4][m + 8];
            }
#pragma unroll
            for (int nf = 0; nf < 4; nf++) {
                int c = wn + nf * 8 + g;
                bf[nf][0] = Bs[buf][c][ks + lq];
                bf[nf][1] = Bs[buf][c][ks + lq + 4];
            }
#pragma unroll
            for (int mf = 0; mf < 4; mf++)
#pragma unroll
                for (int nf = 0; nf < 4; nf++)
                    mma8(acc[mf][nf], af[mf][0], af[mf][1], af[mf][2], af[mf][3],
                         bf[nf][0], bf[nf][1]);
        }
        __syncthreads();
    }
#undef LOAD_CM

    float* Yb = Y + (size_t)b * N * Cout;
#pragma unroll
    for (int mf = 0; mf < 4; mf++) {
#pragma unroll
        for (int nf = 0; nf < 4; nf++) {
            int co = c0 + wn + nf * 8 + lq * 2;
            float b0v = bias[co], b1v = bias[co + 1];
#pragma unroll
            for (int hr = 0; hr < 2; hr++) {
                int m = m0 + wm + mf * 16 + g + hr * 8;
                float v0 = acc[mf][nf][hr * 2 + 0] + b0v;
                float v1 = acc[mf][nf][hr * 2 + 1] + b1v;
                if (act == 1) {
                    v0 = v0 / (1.f + expf(-v0));
                    v1 = v1 / (1.f + expf(-v1));
                }
                *(float2*)(Yb + (size_t)m * Cout + co) = make_float2(v0, v1);
            }
        }
    }
}

// ---------------- tensor-core GEMM: row-major A, channel-major fused out ----------------
// val[b,m,co] = sum_k X[b,m,k]*W[co,k] + bias[co]
// mode 0: out[b,co,m] = resid1 + val*s1[co]
// mode 1: out[b,co,m] = resid1 + (resid2 + val*s1[co]) * s2[co]
__global__ void gemm_rmA_tc(const float* __restrict__ X, const float* __restrict__ W,
                            const float* __restrict__ bias,
                            const float* __restrict__ resid1, const float* __restrict__ resid2,
                            const float* __restrict__ scal1, const float* __restrict__ scal2,
                            float* __restrict__ out, int N, int F, int Cout, int mode) {
    int b = blockIdx.z;
    int m0 = blockIdx.x * BM;
    int c0 = blockIdx.y * BN;
    __shared__ float As[2][BM][PITCHR];  // [m][k]
    __shared__ float Bs[2][BN][PITCHR];  // [co][k]
    int tid = threadIdx.x;
    int warp = tid >> 5, lane = tid & 31;
    int g = lane >> 2, lq = lane & 3;
    int wm = (warp >> 2) * 64;
    int wn = (warp & 3) * 32;
    float acc[4][4][4] = {};
    const float* Xb = X + (size_t)b * N * F;
    int nslab = F / KS;

#define LOAD_RM(slab, buf)                                                                  \
    {                                                                                       \
        int kk0 = (slab)*KS;                                                                \
        _Pragma("unroll") for (int p = 0; p < 2; p++) {                                     \
            int c = tid + p * 256;                                                          \
            int r = c >> 2, kk = (c & 3) << 2;                                              \
            cp_async16(&As[buf][r][kk], Xb + (size_t)(m0 + r) * F + kk0 + kk);              \
            cp_async16(&Bs[buf][r][kk], W + (size_t)(c0 + r) * F + kk0 + kk);               \
        }                                                                                   \
        cp_commit();                                                                        \
    }

    LOAD_RM(0, 0);
    for (int s = 0; s < nslab; s++) {
        int buf = s & 1;
        if (s + 1 < nslab) {
            LOAD_RM(s + 1, buf ^ 1);
            cp_wait1();
        } else {
            cp_wait0();
        }
        __syncthreads();
#pragma unroll
        for (int ks = 0; ks < KS; ks += 8) {
            float af[4][4], bf[4][2];
#pragma unroll
            for (int mf = 0; mf < 4; mf++) {
                int m = wm + mf * 16 + g;
                af[mf][0] = As[buf][m][ks + lq];
                af[mf][1] = As[buf][m + 8][ks + lq];
                af[mf][2] = As[buf][m][ks + lq + 4];
                af[mf][3] = As[buf][m + 8][ks + lq + 4];
            }
#pragma unroll
            for (int nf = 0; nf < 4; nf++) {
                int c = wn + nf * 8 + g;
                bf[nf][0] = Bs[buf][c][ks + lq];
                bf[nf][1] = Bs[buf][c][ks + lq + 4];
            }
#pragma unroll
            for (int mf = 0; mf < 4; mf++)
#pragma unroll
                for (int nf = 0; nf < 4; nf++)
                    mma8(acc[mf][nf], af[mf][0], af[mf][1], af[mf][2], af[mf][3],
                         bf[nf][0], bf[nf][1]);
        }
        __syncthreads();
    }
#undef LOAD_RM

#pragma unroll
    for (int nf = 0; nf < 4; nf++) {
#pragma unroll
        for (int cj = 0; cj < 2; cj++) {
            int co = c0 + wn + nf * 8 + lq * 2 + cj;
            float bv = bias[co];
            float s1 = scal1[co];
            float s2 = (mode == 1) ? scal2[co] : 0.f;
#pragma unroll
            for (int mf = 0; mf < 4; mf++) {
#pragma unroll
                for (int hr = 0; hr < 2; hr++) {
                    int m = m0 + wm + mf * 16 + g + hr * 8;
                    size_t idx = ((size_t)b * Cout + co) * (size_t)N + m;
                    float val = acc[mf][nf][hr * 2 + cj] + bv;
                    if (mode == 0)
                        out[idx] = resid1[idx] + val * s1;
                    else
                        out[idx] = resid1[idx] + (resid2[idx] + val * s1) * s2;
                }
            }
        }
    }
}

// ---------------- LayerNorm + elu+1 (in place on (rows, C)) ----------------
__global__ void ln_elu_kernel(float* __restrict__ x, const float* __restrict__ w,
                              const float* __restrict__ bvec) {
    int r = blockIdx.x;
    float* p = x + (size_t)r * Cn;
    int t = threadIdx.x;  // 128
    float v0 = p[t], v1 = p[t + 128], v2 = p[t + 256];
    float s = v0 + v1 + v2;
    float s2 = v0 * v0 + v1 * v1 + v2 * v2;
    __shared__ float red[128];
    red[t] = s;
    __syncthreads();
    for (int st = 64; st > 0; st >>= 1) {
        if (t < st) red[t] += red[t + st];
        __syncthreads();
    }
    float mu = red[0] * (1.f / (float)Cn);
    __syncthreads();
    red[t] = s2;
    __syncthreads();
    for (int st = 64; st > 0; st >>= 1) {
        if (t < st) red[t] += red[t + st];
        __syncthreads();
    }
    float var = red[0] * (1.f / (float)Cn) - mu * mu;
    float inv = rsqrtf(var + LN_EPS);
    float y;
    y = (v0 - mu) * inv * w[t] + bvec[t];
    p[t] = (y > 0.f) ? y + 1.f : expf(y);
    y = (v1 - mu) * inv * w[t + 128] + bvec[t + 128];
    p[t + 128] = (y > 0.f) ? y + 1.f : expf(y);
    y = (v2 - mu) * inv * w[t + 256] + bvec[t + 256];
    p[t + 256] = (y > 0.f) ? y + 1.f : expf(y);
}

// ---------------- kv_sum + k_sum per (b,h) ----------------
__global__ void kv_kernel(const float* __restrict__ k, const float* __restrict__ v,
                          float* __restrict__ kv, float* __restrict__ ksum) {
    int bh = blockIdx.x;
    int b = bh / Hn, h = bh % Hn;
    __shared__ float ks[32][Dn];
    __shared__ float vs[32][Dn];
    int tid = threadIdx.x;  // 256
    float acc[9] = {};
    float ksacc = 0.f;
    for (int n0 = 0; n0 < NK; n0 += 32) {
        for (int i = tid; i < 32 * Dn; i += 256) {
            int nn = i / Dn, dd = i % Dn;
            size_t base = ((size_t)b * NK + n0 + nn) * Cn + h * Dn + dd;
            ks[nn][dd] = k[base];
            vs[nn][dd] = v[base];
        }
        __syncthreads();
#pragma unroll 4
        for (int nn = 0; nn < 32; nn++) {
#pragma unroll
            for (int o = 0; o < 9; o++) {
                int idx = tid + o * 256;
                int dd = idx / Dn, ee = idx % Dn;
                acc[o] += ks[nn][dd] * vs[nn][ee];
            }
            if (tid < Dn) ksacc += ks[nn][tid];
        }
        __syncthreads();
    }
#pragma unroll
    for (int o = 0; o < 9; o++) kv[(size_t)bh * Dn * Dn + tid + o * 256] = acc[o];
    if (tid < Dn) ksum[bh * Dn + tid] = ksacc;
}

// ---------------- attention: num/den ----------------
__global__ void attn_kernel(const float* __restrict__ q, const float* __restrict__ kv,
                            const float* __restrict__ ksum, float* __restrict__ attn) {
    int bh = blockIdx.y;
    int b = bh / Hn, h = bh % Hn;
    int n0 = blockIdx.x * 64;
    __shared__ float kvs[Dn][Dn];
    __shared__ float kss[Dn];
    __shared__ float qs[64][Dn];
    __shared__ float dens[64];
    int tid = threadIdx.x;  // 256
    for (int i = tid; i < Dn * Dn; i += 256) kvs[i / Dn][i % Dn] = kv[(size_t)bh * Dn * Dn + i];
    if (tid < Dn) kss[tid] = ksum[bh * Dn + tid];
    for (int i = tid; i < 64 * Dn; i += 256) {
        int nn = i / Dn, dd = i % Dn;
        qs[nn][dd] = q[((size_t)b * NQ + n0 + nn) * Cn + h * Dn + dd];
    }
    __syncthreads();
    if (tid < 64) {
        float den = 0.f;
#pragma unroll
        for (int dd = 0; dd < Dn; dd++) den += qs[tid][dd] * kss[dd];
        dens[tid] = den + 1e-8f;
    }
    __syncthreads();
#pragma unroll
    for (int o = 0; o < 12; o++) {
        int idx = tid + o * 256;
        int nn = idx / Dn, ee = idx % Dn;
        float sacc = 0.f;
#pragma unroll
        for (int dd = 0; dd < Dn; dd++) sacc += qs[nn][dd] * kvs[dd][ee];
        attn[((size_t)b * NQ + n0 + nn) * Cn + h * Dn + ee] = sacc / dens[nn];
    }
}

// ---------------- host launch ----------------
extern "C" void kernel_launch(void* const* d_in, const int* in_sizes, int n_in,
                              void* d_out, int out_size) {
    const float* query = (const float*)d_in[0];
    const float* key = (const float*)d_in[1];
    const float* value = (const float*)d_in[2];
    const float* ada_gamma = (const float*)d_in[3];
    const float* ada_beta = (const float*)d_in[4];
    const float* Wq = (const float*)d_in[5];
    const float* bq = (const float*)d_in[6];
    const float* Wk = (const float*)d_in[7];
    const float* bk = (const float*)d_in[8];
    const float* Wv = (const float*)d_in[9];
    const float* bv = (const float*)d_in[10];
    const float* Wo = (const float*)d_in[11];
    const float* bo = (const float*)d_in[12];
    const float* lnq_w = (const float*)d_in[13];
    const float* lnq_b = (const float*)d_in[14];
    const float* lnk_w = (const float*)d_in[15];
    const float* lnk_b = (const float*)d_in[16];
    const float* attn_scalar = (const float*)d_in[17];
    const float* ffn_gamma = (const float*)d_in[18];
    const float* ffn_beta = (const float*)d_in[19];
    const float* W1 = (const float*)d_in[20];
    const float* b1 = (const float*)d_in[21];
    const float* W2 = (const float*)d_in[22];
    const float* b2 = (const float*)d_in[23];
    const float* ffn_scalar = (const float*)d_in[24];
    const float* final_scalar = (const float*)d_in[25];
    float* out = (float*)d_out;

    float *ada, *q, *k, *v, *attn, *working, *normed, *hbuf, *kv, *ksum, *gx, *meanc;
    cudaGetSymbolAddress((void**)&ada, g_ada);
    cudaGetSymbolAddress((void**)&q, g_q);
    cudaGetSymbolAddress((void**)&k, g_k);
    cudaGetSymbolAddress((void**)&v, g_v);
    cudaGetSymbolAddress((void**)&attn, g_attn);
    cudaGetSymbolAddress((void**)&working, g_working);
    cudaGetSymbolAddress((void**)&normed, g_normed);
    cudaGetSymbolAddress((void**)&hbuf, g_h);
    cudaGetSymbolAddress((void**)&kv, g_kv);
    cudaGetSymbolAddress((void**)&ksum, g_ksum);
    cudaGetSymbolAddress((void**)&gx, g_gx);
    cudaGetSymbolAddress((void**)&meanc, g_meanc);

    // 1) GRN on query -> ada
    grn_reduce_kernel<<<Bn * Cn, 256>>>(query, gx, NQ);
    grn_mean_kernel<<<Bn, 128>>>(gx, meanc);
    grn_apply_kernel<<<2048, 256>>>(query, gx, meanc, ada_gamma, ada_beta, ada);

    // 2) projections (tensor core tf32, cp.async pipelined)
    gemm_cmA_tc<<<dim3(NQ / BM, Cn / BN, Bn), 256>>>(ada, Wq, bq, q, NQ, Cn, Cn, 0);
    gemm_cmA_tc<<<dim3(NK / BM, Cn / BN, Bn), 256>>>(key, Wk, bk, k, NK, Cn, Cn, 0);
    gemm_cmA_tc<<<dim3(NK / BM, Cn / BN, Bn), 256>>>(value, Wv, bv, v, NK, Cn, Cn, 0);

    // 3) LN + elu+1 (in place)
    ln_elu_kernel<<<Bn * NQ, 128>>>(q, lnq_w, lnq_b);
    ln_elu_kernel<<<Bn * NK, 128>>>(k, lnk_w, lnk_b);

    // 4) kv_sum, k_sum
    kv_kernel<<<Bn * Hn, 256>>>(k, v, kv, ksum);

    // 5) linear attention num/den
    attn_kernel<<<dim3(NQ / 64, Bn * Hn), 256>>>(q, kv, ksum, attn);

    // 6) Wo projection + attn residual -> working (channel-major)
    gemm_rmA_tc<<<dim3(NQ / BM, Cn / BN, Bn), 256>>>(attn, Wo, bo, query, nullptr,
                                                     attn_scalar, nullptr, working,
                                                     NQ, Cn, Cn, 0);

    // 7) GRN on working -> normed
    grn_reduce_kernel<<<Bn * Cn, 256>>>(working, gx, NQ);
    grn_mean_kernel<<<Bn, 128>>>(gx, meanc);
    grn_apply_kernel<<<2048, 256>>>(working, gx, meanc, ffn_gamma, ffn_beta, normed);

    // 8) FFN1 (+silu) -> h
    gemm_cmA_tc<<<dim3(NQ / BM, Fn / BN, Bn), 256>>>(normed, W1, b1, hbuf, NQ, Cn, Fn, 1);

    // 9) FFN2 + ffn residual + final residual -> out
    gemm_rmA_tc<<<dim3(NQ / BM, Cn / BN, Bn), 256>>>(hbuf, W2, b2, query, working,
                                                     ffn_scalar, final_scalar, out,
                                                     NQ, Fn, Cn, 1);
}